// round 1
// baseline (speedup 1.0000x reference)
#include <cuda_runtime.h>
#include <math.h>

#define D_MODEL 1024
#define D_STATE 16
#define D_CONV  4
#define DT_RANK 32
#define D_INNER 2048
#define BATCH   4
#define SEQ     2048
#define M_TOTAL (BATCH * SEQ)          // 8192
#define NCHUNK  16
#define CHUNK_LEN (SEQ / NCHUNK)       // 128

// ---------------- scratch (device globals; no allocation allowed) ----------
__device__ float g_xz[(size_t)M_TOTAL * 2 * D_INNER];   // 134 MB: [x_in | z]
__device__ float g_u [(size_t)M_TOTAL * D_INNER];       // 67 MB  conv+silu out
__device__ float g_dt[(size_t)M_TOTAL * D_INNER];       // 67 MB  softplus(dt)
__device__ float g_g [(size_t)M_TOTAL * D_INNER];       // 67 MB  y * silu(z)
__device__ float g_A [D_INNER * D_STATE];               // -exp(A_log)
__device__ float g_hfin[(size_t)BATCH * D_INNER * NCHUNK * D_STATE];
__device__ float g_cum [(size_t)BATCH * D_INNER * NCHUNK * D_STATE];
__device__ float g_hin [(size_t)BATCH * D_INNER * NCHUNK * D_STATE];
__device__ float g_dvmean;

// ---------------- prep: A = -exp(A_log), dvmean = mean(Dv) -----------------
__global__ void prep_kernel(const float* __restrict__ A_log,
                            const float* __restrict__ Dv) {
    int i = blockIdx.x * blockDim.x + threadIdx.x;
    if (i < D_INNER * D_STATE) g_A[i] = -__expf(A_log[i]);
    if (blockIdx.x == 0) {
        __shared__ float sdata[256];
        float s = 0.f;
        for (int j = threadIdx.x; j < D_INNER; j += 256) s += Dv[j];
        sdata[threadIdx.x] = s;
        __syncthreads();
        for (int o = 128; o > 0; o >>= 1) {
            if (threadIdx.x < o) sdata[threadIdx.x] += sdata[threadIdx.x + o];
            __syncthreads();
        }
        if (threadIdx.x == 0) g_dvmean = sdata[0] / (float)D_INNER;
    }
}

// ---------------- SGEMM: C[M,N] = A[M,K] @ B[N,K]^T + bias (+ resid) -------
// 128x128 tile, BK=16, 256 threads, 8x8 microtile
__global__ __launch_bounds__(256)
void sgemm_bias(const float* __restrict__ Ag, const float* __restrict__ Bg,
                const float* __restrict__ bias, float* __restrict__ C,
                int M, int N, int K,
                const float* __restrict__ resid, int use_resid) {
    __shared__ float As[16][128];
    __shared__ float Bs[16][128];
    int tid = threadIdx.x;
    int m0 = blockIdx.y * 128;
    int n0 = blockIdx.x * 128;
    int tx = tid & 15, ty = tid >> 4;

    float acc[8][8];
#pragma unroll
    for (int i = 0; i < 8; i++)
#pragma unroll
        for (int j = 0; j < 8; j++) acc[i][j] = 0.f;

    int lrow = tid >> 2;        // 0..63
    int lk   = (tid & 3) * 4;   // 0,4,8,12

    for (int k0 = 0; k0 < K; k0 += 16) {
#pragma unroll
        for (int it = 0; it < 2; it++) {
            int r = lrow + it * 64;
            float4 va = *(const float4*)(Ag + (size_t)(m0 + r) * K + k0 + lk);
            As[lk + 0][r] = va.x; As[lk + 1][r] = va.y;
            As[lk + 2][r] = va.z; As[lk + 3][r] = va.w;
            float4 vb = *(const float4*)(Bg + (size_t)(n0 + r) * K + k0 + lk);
            Bs[lk + 0][r] = vb.x; Bs[lk + 1][r] = vb.y;
            Bs[lk + 2][r] = vb.z; Bs[lk + 3][r] = vb.w;
        }
        __syncthreads();
#pragma unroll
        for (int k = 0; k < 16; k++) {
            float a[8], b[8];
#pragma unroll
            for (int i = 0; i < 8; i++) a[i] = As[k][ty * 8 + i];
#pragma unroll
            for (int j = 0; j < 8; j++) b[j] = Bs[k][tx * 8 + j];
#pragma unroll
            for (int i = 0; i < 8; i++)
#pragma unroll
                for (int j = 0; j < 8; j++) acc[i][j] += a[i] * b[j];
        }
        __syncthreads();
    }

    float dvm = use_resid ? g_dvmean : 0.f;
#pragma unroll
    for (int i = 0; i < 8; i++) {
        int m = m0 + ty * 8 + i;
#pragma unroll
        for (int j = 0; j < 8; j++) {
            int n = n0 + tx * 8 + j;
            float v = acc[i][j] + bias[n];
            if (use_resid) v += resid[(size_t)m * N + n] * dvm;
            C[(size_t)m * N + n] = v;
        }
    }
}

// ---------------- depthwise causal conv (K=4) + bias + SiLU -> u -----------
__global__ void conv_silu_kernel(const float* __restrict__ conv_w,
                                 const float* __restrict__ conv_b) {
    int m = blockIdx.x;            // 0..8191
    int t = m & (SEQ - 1);
    for (int d = threadIdx.x; d < D_INNER; d += blockDim.x) {
        float w0 = conv_w[d * 4 + 0], w1 = conv_w[d * 4 + 1];
        float w2 = conv_w[d * 4 + 2], w3 = conv_w[d * 4 + 3];
        float acc = conv_b[d];
        // out[t] = sum_k x[t-3+k] * w[k]
        if (t >= 3) acc += g_xz[(size_t)(m - 3) * (2 * D_INNER) + d] * w0;
        if (t >= 2) acc += g_xz[(size_t)(m - 2) * (2 * D_INNER) + d] * w1;
        if (t >= 1) acc += g_xz[(size_t)(m - 1) * (2 * D_INNER) + d] * w2;
        acc += g_xz[(size_t)m * (2 * D_INNER) + d] * w3;
        float s = acc / (1.f + __expf(-acc));          // silu
        g_u[(size_t)m * D_INNER + d] = s;
    }
}

// ---------------- dt = softplus(x_in[:, :32] @ Wdt^T + bdt) ----------------
// block handles 16 consecutive rows (m), 256 threads sweep n
__global__ __launch_bounds__(256)
void dt_kernel(const float* __restrict__ Wdt, const float* __restrict__ bdt) {
    int m0 = blockIdx.x * 16;
    __shared__ float xs[16][32];
    int tid = threadIdx.x;
    for (int i = tid; i < 16 * 32; i += 256)
        xs[i >> 5][i & 31] = g_xz[(size_t)(m0 + (i >> 5)) * (2 * D_INNER) + (i & 31)];
    __syncthreads();
    for (int n = tid; n < D_INNER; n += 256) {
        float w[32];
#pragma unroll
        for (int k = 0; k < 32; k++) w[k] = Wdt[n * 32 + k];
        float bv = bdt[n];
#pragma unroll
        for (int mm = 0; mm < 16; mm++) {
            float acc = bv;
#pragma unroll
            for (int k = 0; k < 32; k++) acc += xs[mm][k] * w[k];
            float sp = (acc > 20.f) ? acc : log1pf(__expf(acc));
            g_dt[(size_t)(m0 + mm) * D_INNER + n] = sp;
        }
    }
}

// ---------------- scan pass 1: per-chunk local scan (h_in = 0) -------------
__global__ __launch_bounds__(256)
void scan1_kernel(const float* __restrict__ Bm) {
    int d = blockIdx.x * blockDim.x + threadIdx.x;   // 0..2047
    int b = blockIdx.y;
    int c = blockIdx.z;
    float Av[D_STATE], Bv[D_STATE], h[D_STATE], cum[D_STATE];
#pragma unroll
    for (int n = 0; n < D_STATE; n++) {
        Av[n] = g_A[d * D_STATE + n];
        Bv[n] = Bm[d * D_STATE + n];
        h[n] = 0.f; cum[n] = 1.f;
    }
    int t0 = c * CHUNK_LEN;
    for (int t = t0; t < t0 + CHUNK_LEN; t++) {
        size_t idx = (size_t)(b * SEQ + t) * D_INNER + d;
        float dtv = g_dt[idx];
        float dbu = dtv * g_u[idx];
#pragma unroll
        for (int n = 0; n < D_STATE; n++) {
            float dA = __expf(dtv * Av[n]);
            h[n] = h[n] * dA + dbu * Bv[n];
            cum[n] *= dA;
        }
    }
    size_t o = (((size_t)(b * D_INNER + d)) * NCHUNK + c) * D_STATE;
#pragma unroll
    for (int n = 0; n < D_STATE; n++) { g_hfin[o + n] = h[n]; g_cum[o + n] = cum[n]; }
}

// ---------------- sequential combine over chunks (cheap) -------------------
__global__ __launch_bounds__(256)
void combine_kernel() {
    int d = blockIdx.x * blockDim.x + threadIdx.x;
    int b = blockIdx.y;
    float H[D_STATE];
#pragma unroll
    for (int n = 0; n < D_STATE; n++) H[n] = 0.f;
    size_t base = ((size_t)(b * D_INNER + d)) * NCHUNK * D_STATE;
    for (int c = 0; c < NCHUNK; c++) {
        size_t o = base + (size_t)c * D_STATE;
#pragma unroll
        for (int n = 0; n < D_STATE; n++) g_hin[o + n] = H[n];
#pragma unroll
        for (int n = 0; n < D_STATE; n++) H[n] = g_hfin[o + n] + g_cum[o + n] * H[n];
    }
}

// ---------------- scan pass 2: full scan with correct h_in; g = y*silu(z) --
__global__ __launch_bounds__(256)
void scan2_kernel(const float* __restrict__ Bm, const float* __restrict__ Cm) {
    int d = blockIdx.x * blockDim.x + threadIdx.x;
    int b = blockIdx.y;
    int c = blockIdx.z;
    float Av[D_STATE], Bv[D_STATE], Cv[D_STATE], h[D_STATE];
    size_t o = (((size_t)(b * D_INNER + d)) * NCHUNK + c) * D_STATE;
#pragma unroll
    for (int n = 0; n < D_STATE; n++) {
        Av[n] = g_A[d * D_STATE + n];
        Bv[n] = Bm[d * D_STATE + n];
        Cv[n] = Cm[d * D_STATE + n];
        h[n] = g_hin[o + n];
    }
    int t0 = c * CHUNK_LEN;
    for (int t = t0; t < t0 + CHUNK_LEN; t++) {
        size_t idx = (size_t)(b * SEQ + t) * D_INNER + d;
        float dtv = g_dt[idx];
        float dbu = dtv * g_u[idx];
        float y = 0.f;
#pragma unroll
        for (int n = 0; n < D_STATE; n++) {
            float dA = __expf(dtv * Av[n]);
            h[n] = h[n] * dA + dbu * Bv[n];
            y += h[n] * Cv[n];
        }
        float z = g_xz[(size_t)(b * SEQ + t) * (2 * D_INNER) + D_INNER + d];
        float sz = z / (1.f + __expf(-z));
        g_g[idx] = y * sz;
    }
}

// ---------------- launch ----------------------------------------------------
extern "C" void kernel_launch(void* const* d_in, const int* in_sizes, int n_in,
                              void* d_out, int out_size) {
    const float* x      = (const float*)d_in[0];
    const float* Wi     = (const float*)d_in[1];
    const float* bi     = (const float*)d_in[2];
    const float* conv_w = (const float*)d_in[3];
    const float* conv_b = (const float*)d_in[4];
    const float* Wdt    = (const float*)d_in[5];
    const float* bdt    = (const float*)d_in[6];
    const float* A_log  = (const float*)d_in[7];
    const float* Bm     = (const float*)d_in[8];
    const float* Cm     = (const float*)d_in[9];
    const float* Dv     = (const float*)d_in[10];
    const float* Wo     = (const float*)d_in[11];
    const float* bo     = (const float*)d_in[12];
    float* out = (float*)d_out;

    float *p_xz = nullptr, *p_g = nullptr;
    cudaGetSymbolAddress((void**)&p_xz, g_xz);
    cudaGetSymbolAddress((void**)&p_g,  g_g);

    // 0) prep
    prep_kernel<<<(D_INNER * D_STATE + 255) / 256, 256>>>(A_log, Dv);

    // 1) xz = x @ Wi^T + bi   (M=8192, N=4096, K=1024)
    sgemm_bias<<<dim3((2 * D_INNER) / 128, M_TOTAL / 128), 256>>>(
        x, Wi, bi, p_xz, M_TOTAL, 2 * D_INNER, D_MODEL, nullptr, 0);

    // 2) depthwise conv + silu -> u
    conv_silu_kernel<<<M_TOTAL, 256>>>(conv_w, conv_b);

    // 3) dt = softplus(x_in[:, :32] @ Wdt^T + bdt)
    dt_kernel<<<M_TOTAL / 16, 256>>>(Wdt, bdt);

    // 4) chunked scan
    scan1_kernel<<<dim3(D_INNER / 256, BATCH, NCHUNK), 256>>>(Bm);
    combine_kernel<<<dim3(D_INNER / 256, BATCH), 256>>>();
    scan2_kernel<<<dim3(D_INNER / 256, BATCH, NCHUNK), 256>>>(Bm, Cm);

    // 5) out = g @ Wo^T + bo + x * mean(Dv)   (M=8192, N=1024, K=2048)
    sgemm_bias<<<dim3(D_MODEL / 128, M_TOTAL / 128), 256>>>(
        p_g, Wo, bo, out, M_TOTAL, D_MODEL, D_INNER, x, 1);
}

// round 2
// speedup vs baseline: 2.0788x; 2.0788x over previous
#include <cuda_runtime.h>
#include <math.h>

#define D_MODEL 1024
#define D_STATE 16
#define D_CONV  4
#define DT_RANK 32
#define D_INNER 2048
#define BATCH   4
#define SEQ     2048
#define M_TOTAL (BATCH * SEQ)          // 8192
#define NCHUNK  16
#define CHUNK_LEN (SEQ / NCHUNK)       // 128

// ---------------- scratch (device globals; no allocation allowed) ----------
__device__ float g_xz[(size_t)M_TOTAL * 2 * D_INNER];   // 134 MB: [x_in | z]
__device__ float g_u [(size_t)M_TOTAL * D_INNER];       // 67 MB  conv+silu out
__device__ float g_dt[(size_t)M_TOTAL * D_INNER];       // 67 MB  softplus(dt)
__device__ float g_g [(size_t)M_TOTAL * D_INNER];       // 67 MB  y * silu(z)
__device__ float g_A [D_INNER * D_STATE];               // -exp(A_log)
__device__ float g_hfin[(size_t)BATCH * D_INNER * NCHUNK * D_STATE];
__device__ float g_cum [(size_t)BATCH * D_INNER * NCHUNK * D_STATE];
__device__ float g_hin [(size_t)BATCH * D_INNER * NCHUNK * D_STATE];
__device__ float g_dvmean;

// ---------------- prep: A = -exp(A_log), dvmean = mean(Dv) -----------------
__global__ void prep_kernel(const float* __restrict__ A_log,
                            const float* __restrict__ Dv) {
    int i = blockIdx.x * blockDim.x + threadIdx.x;
    if (i < D_INNER * D_STATE) g_A[i] = -__expf(A_log[i]);
    if (blockIdx.x == 0) {
        __shared__ float sdata[256];
        float s = 0.f;
        for (int j = threadIdx.x; j < D_INNER; j += 256) s += Dv[j];
        sdata[threadIdx.x] = s;
        __syncthreads();
        for (int o = 128; o > 0; o >>= 1) {
            if (threadIdx.x < o) sdata[threadIdx.x] += sdata[threadIdx.x + o];
            __syncthreads();
        }
        if (threadIdx.x == 0) g_dvmean = sdata[0] / (float)D_INNER;
    }
}

// ---------------- tf32 tensor-core GEMM ------------------------------------
// C[M,N] = A[M,K] @ B[N,K]^T + bias (+ resid*dvmean)
// 128x128 block tile, BK=32, 256 threads (8 warps, 2Mx4N), warp tile 64x32,
// mma.sync.m16n8k8.tf32. Smem [row][k] with stride 36 (conflict-free frags).
__device__ __forceinline__ unsigned f2tf(float f) {
    unsigned r;
    asm("cvt.rna.tf32.f32 %0, %1;" : "=r"(r) : "f"(f));
    return r;
}

__global__ __launch_bounds__(256)
void gemm_tf32(const float* __restrict__ Ag, const float* __restrict__ Bg,
               const float* __restrict__ bias, float* __restrict__ C,
               int M, int N, int K,
               const float* __restrict__ resid, int use_resid) {
    __shared__ float As[128][36];
    __shared__ float Bs[128][36];

    const int tid  = threadIdx.x;
    const int lane = tid & 31;
    const int warp = tid >> 5;
    const int wm   = (warp & 1) * 64;   // warp M offset in tile
    const int wn   = (warp >> 1) * 32;  // warp N offset in tile
    const int grp  = lane >> 2;         // 0..7
    const int tig  = lane & 3;          // 0..3

    const int m0 = blockIdx.y * 128;
    const int n0 = blockIdx.x * 128;

    // global-load mapping: 4 rows strided by 32, one float4 of k each
    const int ldr = tid >> 3;           // 0..31
    const int ldc = (tid & 7) * 4;      // 0..28

    float acc[4][4][4];
#pragma unroll
    for (int i = 0; i < 4; i++)
#pragma unroll
        for (int j = 0; j < 4; j++)
#pragma unroll
            for (int c = 0; c < 4; c++) acc[i][j][c] = 0.f;

    float4 ra[4], rb[4];
    // preload k0 = 0
#pragma unroll
    for (int p = 0; p < 4; p++) {
        int r = ldr + p * 32;
        ra[p] = *(const float4*)(Ag + (size_t)(m0 + r) * K + ldc);
        rb[p] = *(const float4*)(Bg + (size_t)(n0 + r) * K + ldc);
    }

    for (int k0 = 0; k0 < K; k0 += 32) {
        // store (tf32-rounded) to smem
#pragma unroll
        for (int p = 0; p < 4; p++) {
            int r = ldr + p * 32;
            float4 va, vb;
            va.x = __uint_as_float(f2tf(ra[p].x));
            va.y = __uint_as_float(f2tf(ra[p].y));
            va.z = __uint_as_float(f2tf(ra[p].z));
            va.w = __uint_as_float(f2tf(ra[p].w));
            vb.x = __uint_as_float(f2tf(rb[p].x));
            vb.y = __uint_as_float(f2tf(rb[p].y));
            vb.z = __uint_as_float(f2tf(rb[p].z));
            vb.w = __uint_as_float(f2tf(rb[p].w));
            *(float4*)&As[r][ldc] = va;
            *(float4*)&Bs[r][ldc] = vb;
        }
        __syncthreads();

        // prefetch next k-tile
        if (k0 + 32 < K) {
#pragma unroll
            for (int p = 0; p < 4; p++) {
                int r = ldr + p * 32;
                ra[p] = *(const float4*)(Ag + (size_t)(m0 + r) * K + k0 + 32 + ldc);
                rb[p] = *(const float4*)(Bg + (size_t)(n0 + r) * K + k0 + 32 + ldc);
            }
        }

        // compute on smem tile
#pragma unroll
        for (int ks = 0; ks < 4; ks++) {
            const int kb = ks * 8;
            unsigned b0[4], b1[4];
#pragma unroll
            for (int j = 0; j < 4; j++) {
                const float* Bb = &Bs[wn + 8 * j + grp][kb + tig];
                b0[j] = __float_as_uint(Bb[0]);
                b1[j] = __float_as_uint(Bb[4]);
            }
#pragma unroll
            for (int i = 0; i < 4; i++) {
                const float* Ab = &As[wm + 16 * i + grp][kb + tig];
                unsigned a0 = __float_as_uint(Ab[0]);
                unsigned a1 = __float_as_uint(Ab[8 * 36]);
                unsigned a2 = __float_as_uint(Ab[4]);
                unsigned a3 = __float_as_uint(Ab[8 * 36 + 4]);
#pragma unroll
                for (int j = 0; j < 4; j++) {
                    asm volatile(
                        "mma.sync.aligned.m16n8k8.row.col.f32.tf32.tf32.f32 "
                        "{%0,%1,%2,%3}, {%4,%5,%6,%7}, {%8,%9}, {%0,%1,%2,%3};"
                        : "+f"(acc[i][j][0]), "+f"(acc[i][j][1]),
                          "+f"(acc[i][j][2]), "+f"(acc[i][j][3])
                        : "r"(a0), "r"(a1), "r"(a2), "r"(a3),
                          "r"(b0[j]), "r"(b1[j]));
                }
            }
        }
        __syncthreads();
    }

    // epilogue
    const float dvm = use_resid ? g_dvmean : 0.f;
#pragma unroll
    for (int i = 0; i < 4; i++) {
        int m = m0 + wm + 16 * i + grp;
#pragma unroll
        for (int j = 0; j < 4; j++) {
            int n = n0 + wn + 8 * j + 2 * tig;
            float bn0 = bias[n], bn1 = bias[n + 1];
            float v0 = acc[i][j][0] + bn0;
            float v1 = acc[i][j][1] + bn1;
            float v2 = acc[i][j][2] + bn0;
            float v3 = acc[i][j][3] + bn1;
            if (use_resid) {
                v0 += resid[(size_t)m * N + n] * dvm;
                v1 += resid[(size_t)m * N + n + 1] * dvm;
                v2 += resid[(size_t)(m + 8) * N + n] * dvm;
                v3 += resid[(size_t)(m + 8) * N + n + 1] * dvm;
            }
            *(float2*)(C + (size_t)m * N + n)       = make_float2(v0, v1);
            *(float2*)(C + (size_t)(m + 8) * N + n) = make_float2(v2, v3);
        }
    }
}

// ---------------- depthwise causal conv (K=4) + bias + SiLU -> u -----------
__global__ void conv_silu_kernel(const float* __restrict__ conv_w,
                                 const float* __restrict__ conv_b) {
    int m = blockIdx.x;            // 0..8191
    int t = m & (SEQ - 1);
    for (int d = threadIdx.x; d < D_INNER; d += blockDim.x) {
        float w0 = conv_w[d * 4 + 0], w1 = conv_w[d * 4 + 1];
        float w2 = conv_w[d * 4 + 2], w3 = conv_w[d * 4 + 3];
        float acc = conv_b[d];
        if (t >= 3) acc += g_xz[(size_t)(m - 3) * (2 * D_INNER) + d] * w0;
        if (t >= 2) acc += g_xz[(size_t)(m - 2) * (2 * D_INNER) + d] * w1;
        if (t >= 1) acc += g_xz[(size_t)(m - 1) * (2 * D_INNER) + d] * w2;
        acc += g_xz[(size_t)m * (2 * D_INNER) + d] * w3;
        float s = acc / (1.f + __expf(-acc));          // silu
        g_u[(size_t)m * D_INNER + d] = s;
    }
}

// ---------------- dt = softplus(x_in[:, :32] @ Wdt^T + bdt) ----------------
// block handles 16 rows; Wdt staged in shared, per-thread acc[16]
__global__ __launch_bounds__(256)
void dt_kernel(const float* __restrict__ Wdt, const float* __restrict__ bdt) {
    const int m0 = blockIdx.x * 16;
    const int tid = threadIdx.x;
    __shared__ float xs[16][32];
    __shared__ float ws[256][33];       // +1 pad: lane bank = (tid + k) % 32

    for (int i = tid; i < 16 * 32; i += 256)
        xs[i >> 5][i & 31] = g_xz[(size_t)(m0 + (i >> 5)) * (2 * D_INNER) + (i & 31)];

    for (int nt = 0; nt < D_INNER / 256; nt++) {
        __syncthreads();
        for (int i = tid; i < 256 * 32; i += 256)
            ws[i >> 5][i & 31] = Wdt[nt * 256 * 32 + i];
        __syncthreads();

        const int n = nt * 256 + tid;
        float acc[16];
        const float bv = bdt[n];
#pragma unroll
        for (int mm = 0; mm < 16; mm++) acc[mm] = bv;
#pragma unroll
        for (int k = 0; k < 32; k++) {
            float wk = ws[tid][k];
#pragma unroll
            for (int mm = 0; mm < 16; mm++) acc[mm] += xs[mm][k] * wk;
        }
#pragma unroll
        for (int mm = 0; mm < 16; mm++) {
            float a = acc[mm];
            float sp = (a > 20.f) ? a : log1pf(__expf(a));
            g_dt[(size_t)(m0 + mm) * D_INNER + n] = sp;
        }
    }
}

// ---------------- scan pass 1: per-chunk local scan (h_in = 0) -------------
__global__ __launch_bounds__(256)
void scan1_kernel(const float* __restrict__ Bm) {
    int d = blockIdx.x * blockDim.x + threadIdx.x;   // 0..2047
    int b = blockIdx.y;
    int c = blockIdx.z;
    float Av[D_STATE], Bv[D_STATE], h[D_STATE], cum[D_STATE];
#pragma unroll
    for (int n = 0; n < D_STATE; n++) {
        Av[n] = g_A[d * D_STATE + n];
        Bv[n] = Bm[d * D_STATE + n];
        h[n] = 0.f; cum[n] = 1.f;
    }
    int t0 = c * CHUNK_LEN;
    for (int t = t0; t < t0 + CHUNK_LEN; t++) {
        size_t idx = (size_t)(b * SEQ + t) * D_INNER + d;
        float dtv = g_dt[idx];
        float dbu = dtv * g_u[idx];
#pragma unroll
        for (int n = 0; n < D_STATE; n++) {
            float dA = __expf(dtv * Av[n]);
            h[n] = h[n] * dA + dbu * Bv[n];
            cum[n] *= dA;
        }
    }
    size_t o = (((size_t)(b * D_INNER + d)) * NCHUNK + c) * D_STATE;
#pragma unroll
    for (int n = 0; n < D_STATE; n++) { g_hfin[o + n] = h[n]; g_cum[o + n] = cum[n]; }
}

// ---------------- sequential combine over chunks (cheap) -------------------
__global__ __launch_bounds__(256)
void combine_kernel() {
    int d = blockIdx.x * blockDim.x + threadIdx.x;
    int b = blockIdx.y;
    float H[D_STATE];
#pragma unroll
    for (int n = 0; n < D_STATE; n++) H[n] = 0.f;
    size_t base = ((size_t)(b * D_INNER + d)) * NCHUNK * D_STATE;
    for (int c = 0; c < NCHUNK; c++) {
        size_t o = base + (size_t)c * D_STATE;
#pragma unroll
        for (int n = 0; n < D_STATE; n++) g_hin[o + n] = H[n];
#pragma unroll
        for (int n = 0; n < D_STATE; n++) H[n] = g_hfin[o + n] + g_cum[o + n] * H[n];
    }
}

// ---------------- scan pass 2: full scan with correct h_in; g = y*silu(z) --
__global__ __launch_bounds__(256)
void scan2_kernel(const float* __restrict__ Bm, const float* __restrict__ Cm) {
    int d = blockIdx.x * blockDim.x + threadIdx.x;
    int b = blockIdx.y;
    int c = blockIdx.z;
    float Av[D_STATE], Bv[D_STATE], Cv[D_STATE], h[D_STATE];
    size_t o = (((size_t)(b * D_INNER + d)) * NCHUNK + c) * D_STATE;
#pragma unroll
    for (int n = 0; n < D_STATE; n++) {
        Av[n] = g_A[d * D_STATE + n];
        Bv[n] = Bm[d * D_STATE + n];
        Cv[n] = Cm[d * D_STATE + n];
        h[n] = g_hin[o + n];
    }
    int t0 = c * CHUNK_LEN;
    for (int t = t0; t < t0 + CHUNK_LEN; t++) {
        size_t idx = (size_t)(b * SEQ + t) * D_INNER + d;
        float dtv = g_dt[idx];
        float dbu = dtv * g_u[idx];
        float y = 0.f;
#pragma unroll
        for (int n = 0; n < D_STATE; n++) {
            float dA = __expf(dtv * Av[n]);
            h[n] = h[n] * dA + dbu * Bv[n];
            y += h[n] * Cv[n];
        }
        float z = g_xz[(size_t)(b * SEQ + t) * (2 * D_INNER) + D_INNER + d];
        float sz = z / (1.f + __expf(-z));
        g_g[idx] = y * sz;
    }
}

// ---------------- launch ----------------------------------------------------
extern "C" void kernel_launch(void* const* d_in, const int* in_sizes, int n_in,
                              void* d_out, int out_size) {
    const float* x      = (const float*)d_in[0];
    const float* Wi     = (const float*)d_in[1];
    const float* bi     = (const float*)d_in[2];
    const float* conv_w = (const float*)d_in[3];
    const float* conv_b = (const float*)d_in[4];
    const float* Wdt    = (const float*)d_in[5];
    const float* bdt    = (const float*)d_in[6];
    const float* A_log  = (const float*)d_in[7];
    const float* Bm     = (const float*)d_in[8];
    const float* Cm     = (const float*)d_in[9];
    const float* Dv     = (const float*)d_in[10];
    const float* Wo     = (const float*)d_in[11];
    const float* bo     = (const float*)d_in[12];
    float* out = (float*)d_out;

    float *p_xz = nullptr, *p_g = nullptr;
    cudaGetSymbolAddress((void**)&p_xz, g_xz);
    cudaGetSymbolAddress((void**)&p_g,  g_g);

    // 0) prep
    prep_kernel<<<(D_INNER * D_STATE + 255) / 256, 256>>>(A_log, Dv);

    // 1) xz = x @ Wi^T + bi   (M=8192, N=4096, K=1024)  — tf32 tensor cores
    gemm_tf32<<<dim3((2 * D_INNER) / 128, M_TOTAL / 128), 256>>>(
        x, Wi, bi, p_xz, M_TOTAL, 2 * D_INNER, D_MODEL, nullptr, 0);

    // 2) depthwise conv + silu -> u
    conv_silu_kernel<<<M_TOTAL, 256>>>(conv_w, conv_b);

    // 3) dt = softplus(x_in[:, :32] @ Wdt^T + bdt)
    dt_kernel<<<M_TOTAL / 16, 256>>>(Wdt, bdt);

    // 4) chunked scan
    scan1_kernel<<<dim3(D_INNER / 256, BATCH, NCHUNK), 256>>>(Bm);
    combine_kernel<<<dim3(D_INNER / 256, BATCH), 256>>>();
    scan2_kernel<<<dim3(D_INNER / 256, BATCH, NCHUNK), 256>>>(Bm, Cm);

    // 5) out = g @ Wo^T + bo + x * mean(Dv)   (M=8192, N=1024, K=2048)
    gemm_tf32<<<dim3(D_MODEL / 128, M_TOTAL / 128), 256>>>(
        p_g, Wo, bo, out, M_TOTAL, D_MODEL, D_INNER, x, 1);
}

// round 6
// speedup vs baseline: 2.9314x; 1.4101x over previous
#include <cuda_runtime.h>
#include <cuda_bf16.h>
#include <cstdint>
#include <math.h>

#define D_MODEL 1024
#define D_STATE 16
#define D_CONV  4
#define DT_RANK 32
#define D_INNER 2048
#define BATCH   4
#define SEQ     2048
#define M_TOTAL (BATCH * SEQ)          // 8192
#define NCHUNK  32
#define CHUNK_LEN (SEQ / NCHUNK)       // 64

typedef unsigned int u32;

// ---------------- scratch (device globals; no allocation allowed) ----------
__device__ float g_xz[(size_t)M_TOTAL * 2 * D_INNER];   // [x_in | z] fp32
__device__ float g_u [(size_t)M_TOTAL * D_INNER];       // conv+silu out
__device__ float g_dt[(size_t)M_TOTAL * D_INNER];       // softplus(dt)
__device__ float g_A [D_INNER * D_STATE];               // -exp(A_log)
__device__ float g_hfin[(size_t)BATCH * D_INNER * NCHUNK * D_STATE];
__device__ float g_cum [(size_t)BATCH * D_INNER * NCHUNK * D_STATE];
__device__ float g_hin [(size_t)BATCH * D_INNER * NCHUNK * D_STATE];
__device__ float g_dvmean;

__device__ __nv_bfloat16 g_xbf  [(size_t)M_TOTAL * D_MODEL];
__device__ __nv_bfloat16 g_wibf [(size_t)2 * D_INNER * D_MODEL];
__device__ __nv_bfloat16 g_wobf [(size_t)D_MODEL * D_INNER];
__device__ __nv_bfloat16 g_wdtbf[(size_t)D_INNER * DT_RANK];
__device__ __nv_bfloat16 g_xdtbf[(size_t)M_TOTAL * DT_RANK];
__device__ __nv_bfloat16 g_gbf  [(size_t)M_TOTAL * D_INNER];  // y*silu(z) bf16

// ---------------- prep: A = -exp(A_log), dvmean = mean(Dv) -----------------
__global__ void prep_kernel(const float* __restrict__ A_log,
                            const float* __restrict__ Dv) {
    int i = blockIdx.x * blockDim.x + threadIdx.x;
    if (i < D_INNER * D_STATE) g_A[i] = -__expf(A_log[i]);
    if (blockIdx.x == 0) {
        __shared__ float sdata[256];
        float s = 0.f;
        for (int j = threadIdx.x; j < D_INNER; j += 256) s += Dv[j];
        sdata[threadIdx.x] = s;
        __syncthreads();
        for (int o = 128; o > 0; o >>= 1) {
            if (threadIdx.x < o) sdata[threadIdx.x] += sdata[threadIdx.x + o];
            __syncthreads();
        }
        if (threadIdx.x == 0) g_dvmean = sdata[0] / (float)D_INNER;
    }
}

// ---------------- fp32 -> bf16 convert (vectorized) ------------------------
__global__ void f2bf_kernel(const float* __restrict__ in,
                            __nv_bfloat16* __restrict__ out, int n4) {
    int i = blockIdx.x * blockDim.x + threadIdx.x;
    if (i < n4) {
        float4 v = ((const float4*)in)[i];
        __nv_bfloat162* o = (__nv_bfloat162*)out + i * 2;
        o[0] = __nv_bfloat162(__float2bfloat16_rn(v.x), __float2bfloat16_rn(v.y));
        o[1] = __nv_bfloat162(__float2bfloat16_rn(v.z), __float2bfloat16_rn(v.w));
    }
}

// x_in[:, :32] slice from g_xz -> bf16 (for dt gemm)
__global__ void xdt_convert_kernel() {
    int i = blockIdx.x * blockDim.x + threadIdx.x;   // over M_TOTAL*32
    if (i < M_TOTAL * DT_RANK) {
        int m = i >> 5, k = i & 31;
        g_xdtbf[i] = __float2bfloat16_rn(g_xz[(size_t)m * (2 * D_INNER) + k]);
    }
}

// ---------------- bf16 tensor-core GEMM ------------------------------------
// C[M,N] = A[M,K] @ B[N,K]^T (+bias, epilogue MODE)
// 128x128 tile, BK=64, 2-stage cp.async, 8 warps (2Mx4N), warp tile 64x32,
// mma.sync.m16n8k16.bf16, 128B-row smem with XOR-16B-chunk swizzle.
// MODE 0: +bias.  MODE 1: +bias+resid*dvmean.  MODE 2: softplus(+bias).
__device__ __forceinline__ int swz(int r, int cu) {
    return r * 32 + ((((cu >> 2) ^ (r & 7)) << 2) | (cu & 3));
}

template <int MODE>
__global__ __launch_bounds__(256)
void gemm_bf16(const __nv_bfloat16* __restrict__ Ag, int lda,
               const __nv_bfloat16* __restrict__ Bg, int ldb,
               const float* __restrict__ bias, float* __restrict__ C,
               int M, int N, int K,
               const float* __restrict__ resid) {
    extern __shared__ __align__(16) unsigned char smem[];
    // layout: A stage0 [16KB] A stage1 [16KB] B stage0 [16KB] B stage1 [16KB]
    const int tid  = threadIdx.x;
    const int lane = tid & 31;
    const int warp = tid >> 5;
    const int wm   = (warp & 1) * 64;
    const int wn   = (warp >> 1) * 32;
    const int grp  = lane >> 2;
    const int tig  = lane & 3;

    const int m0 = blockIdx.y * 128;
    const int n0 = blockIdx.x * 128;

    const u32 sbase = (u32)__cvta_generic_to_shared(smem);

    float acc[4][4][4];
#pragma unroll
    for (int i = 0; i < 4; i++)
#pragma unroll
        for (int j = 0; j < 4; j++)
#pragma unroll
            for (int c = 0; c < 4; c++) acc[i][j][c] = 0.f;

    const int KT = (K + 63) / 64;

    // prefetch k-tile kt into stage st
#define PREFETCH(k0, st)                                                      \
    {                                                                         \
        _Pragma("unroll")                                                     \
        for (int p = 0; p < 4; p++) {                                         \
            int lin = tid + p * 256;                                          \
            int rr = lin >> 3, cc = lin & 7;                                  \
            int kg = (k0) + cc * 8;                                           \
            u32 off = (u32)(rr * 128 + ((cc ^ (rr & 7)) << 4));               \
            const __nv_bfloat16* asrc = Ag + (size_t)(m0 + rr) * lda + kg;    \
            const __nv_bfloat16* bsrc = Bg + (size_t)(n0 + rr) * ldb + kg;    \
            int sz = (kg < K) ? 16 : 0;                                       \
            if (!sz) { asrc = Ag; bsrc = Bg; }                                \
            u32 adst = sbase + (u32)((st) * 16384) + off;                     \
            u32 bdst = sbase + 32768u + (u32)((st) * 16384) + off;            \
            asm volatile("cp.async.cg.shared.global [%0], [%1], 16, %2;"      \
                         :: "r"(adst), "l"(asrc), "r"(sz));                   \
            asm volatile("cp.async.cg.shared.global [%0], [%1], 16, %2;"      \
                         :: "r"(bdst), "l"(bsrc), "r"(sz));                   \
        }                                                                     \
    }

    PREFETCH(0, 0);
    asm volatile("cp.async.commit_group;");

    for (int kt = 0; kt < KT; kt++) {
        asm volatile("cp.async.wait_group 0;");
        __syncthreads();
        if (kt + 1 < KT) {
            PREFETCH((kt + 1) * 64, (kt + 1) & 1);
            asm volatile("cp.async.commit_group;");
        }
        const int st = kt & 1;
        const u32* As32 = (const u32*)(smem + st * 16384);
        const u32* Bs32 = (const u32*)(smem + 32768 + st * 16384);

#pragma unroll
        for (int ks = 0; ks < 4; ks++) {
            const int kb = ks * 8;
            u32 bf0[4], bf1[4];
#pragma unroll
            for (int j = 0; j < 4; j++) {
                int rb = wn + 8 * j + grp;
                bf0[j] = Bs32[swz(rb, kb + tig)];
                bf1[j] = Bs32[swz(rb, kb + tig + 4)];
            }
#pragma unroll
            for (int i = 0; i < 4; i++) {
                int ra = wm + 16 * i + grp;
                u32 af0 = As32[swz(ra,     kb + tig)];
                u32 af1 = As32[swz(ra + 8, kb + tig)];
                u32 af2 = As32[swz(ra,     kb + tig + 4)];
                u32 af3 = As32[swz(ra + 8, kb + tig + 4)];
#pragma unroll
                for (int j = 0; j < 4; j++) {
                    asm volatile(
                        "mma.sync.aligned.m16n8k16.row.col.f32.bf16.bf16.f32 "
                        "{%0,%1,%2,%3}, {%4,%5,%6,%7}, {%8,%9}, {%0,%1,%2,%3};"
                        : "+f"(acc[i][j][0]), "+f"(acc[i][j][1]),
                          "+f"(acc[i][j][2]), "+f"(acc[i][j][3])
                        : "r"(af0), "r"(af1), "r"(af2), "r"(af3),
                          "r"(bf0[j]), "r"(bf1[j]));
                }
            }
        }
        __syncthreads();
    }
#undef PREFETCH

    // epilogue
    const float dvm = (MODE == 1) ? g_dvmean : 0.f;
#pragma unroll
    for (int i = 0; i < 4; i++) {
        int m = m0 + wm + 16 * i + grp;
#pragma unroll
        for (int j = 0; j < 4; j++) {
            int n = n0 + wn + 8 * j + 2 * tig;
            float bn0 = bias[n], bn1 = bias[n + 1];
            float v0 = acc[i][j][0] + bn0;
            float v1 = acc[i][j][1] + bn1;
            float v2 = acc[i][j][2] + bn0;
            float v3 = acc[i][j][3] + bn1;
            if (MODE == 1) {
                v0 += resid[(size_t)m * N + n] * dvm;
                v1 += resid[(size_t)m * N + n + 1] * dvm;
                v2 += resid[(size_t)(m + 8) * N + n] * dvm;
                v3 += resid[(size_t)(m + 8) * N + n + 1] * dvm;
            }
            if (MODE == 2) {
                v0 = (v0 > 20.f) ? v0 : log1pf(__expf(v0));
                v1 = (v1 > 20.f) ? v1 : log1pf(__expf(v1));
                v2 = (v2 > 20.f) ? v2 : log1pf(__expf(v2));
                v3 = (v3 > 20.f) ? v3 : log1pf(__expf(v3));
            }
            *(float2*)(C + (size_t)m * N + n)       = make_float2(v0, v1);
            *(float2*)(C + (size_t)(m + 8) * N + n) = make_float2(v2, v3);
        }
    }
}

// ---------------- depthwise causal conv (K=4) + bias + SiLU -> u -----------
__global__ __launch_bounds__(256)
void conv_silu_kernel(const float* __restrict__ conv_w,
                      const float* __restrict__ conv_b) {
    int d  = blockIdx.x * 256 + threadIdx.x;
    int t0 = blockIdx.y * 8;
    int b  = blockIdx.z;
    const size_t row = (size_t)2 * D_INNER;
    const float* xp = g_xz + (size_t)(b * SEQ) * row + d;

    float w0 = conv_w[d * 4 + 0], w1 = conv_w[d * 4 + 1];
    float w2 = conv_w[d * 4 + 2], w3 = conv_w[d * 4 + 3];
    float bb = conv_b[d];

    float x3 = (t0 >= 3) ? xp[(size_t)(t0 - 3) * row] : 0.f;
    float x2 = (t0 >= 2) ? xp[(size_t)(t0 - 2) * row] : 0.f;
    float x1 = (t0 >= 1) ? xp[(size_t)(t0 - 1) * row] : 0.f;
#pragma unroll
    for (int tt = 0; tt < 8; tt++) {
        float x0 = xp[(size_t)(t0 + tt) * row];
        float a = bb + x3 * w0 + x2 * w1 + x1 * w2 + x0 * w3;
        float s = a / (1.f + __expf(-a));
        g_u[(size_t)(b * SEQ + t0 + tt) * D_INNER + d] = s;
        x3 = x2; x2 = x1; x1 = x0;
    }
}

// ---------------- scan pass 1: per-chunk local scan (h_in = 0) -------------
__global__ __launch_bounds__(256)
void scan1_kernel(const float* __restrict__ Bm) {
    int d = blockIdx.x * blockDim.x + threadIdx.x;
    int b = blockIdx.y;
    int c = blockIdx.z;
    float Av[D_STATE], Bv[D_STATE], h[D_STATE], cum[D_STATE];
#pragma unroll
    for (int n = 0; n < D_STATE; n++) {
        Av[n] = g_A[d * D_STATE + n];
        Bv[n] = Bm[d * D_STATE + n];
        h[n] = 0.f; cum[n] = 1.f;
    }
    int t0 = c * CHUNK_LEN;
    for (int t = t0; t < t0 + CHUNK_LEN; t++) {
        size_t idx = (size_t)(b * SEQ + t) * D_INNER + d;
        float dtv = g_dt[idx];
        float dbu = dtv * g_u[idx];
#pragma unroll
        for (int n = 0; n < D_STATE; n++) {
            float dA = __expf(dtv * Av[n]);
            h[n] = h[n] * dA + dbu * Bv[n];
            cum[n] *= dA;
        }
    }
    size_t o = (((size_t)(b * D_INNER + d)) * NCHUNK + c) * D_STATE;
#pragma unroll
    for (int n = 0; n < D_STATE; n++) { g_hfin[o + n] = h[n]; g_cum[o + n] = cum[n]; }
}

// ---------------- sequential combine over chunks (cheap) -------------------
__global__ __launch_bounds__(256)
void combine_kernel() {
    int d = blockIdx.x * blockDim.x + threadIdx.x;
    int b = blockIdx.y;
    float H[D_STATE];
#pragma unroll
    for (int n = 0; n < D_STATE; n++) H[n] = 0.f;
    size_t base = ((size_t)(b * D_INNER + d)) * NCHUNK * D_STATE;
    for (int c = 0; c < NCHUNK; c++) {
        size_t o = base + (size_t)c * D_STATE;
#pragma unroll
        for (int n = 0; n < D_STATE; n++) g_hin[o + n] = H[n];
#pragma unroll
        for (int n = 0; n < D_STATE; n++) H[n] = g_hfin[o + n] + g_cum[o + n] * H[n];
    }
}

// ---------------- scan pass 2: full scan; g = y*silu(z) -> bf16 ------------
__global__ __launch_bounds__(256)
void scan2_kernel(const float* __restrict__ Bm, const float* __restrict__ Cm) {
    int d = blockIdx.x * blockDim.x + threadIdx.x;
    int b = blockIdx.y;
    int c = blockIdx.z;
    float Av[D_STATE], Bv[D_STATE], Cv[D_STATE], h[D_STATE];
    size_t o = (((size_t)(b * D_INNER + d)) * NCHUNK + c) * D_STATE;
#pragma unroll
    for (int n = 0; n < D_STATE; n++) {
        Av[n] = g_A[d * D_STATE + n];
        Bv[n] = Bm[d * D_STATE + n];
        Cv[n] = Cm[d * D_STATE + n];
        h[n] = g_hin[o + n];
    }
    int t0 = c * CHUNK_LEN;
    for (int t = t0; t < t0 + CHUNK_LEN; t++) {
        size_t idx = (size_t)(b * SEQ + t) * D_INNER + d;
        float dtv = g_dt[idx];
        float dbu = dtv * g_u[idx];
        float y = 0.f;
#pragma unroll
        for (int n = 0; n < D_STATE; n++) {
            float dA = __expf(dtv * Av[n]);
            h[n] = h[n] * dA + dbu * Bv[n];
            y += h[n] * Cv[n];
        }
        float z = g_xz[(size_t)(b * SEQ + t) * (2 * D_INNER) + D_INNER + d];
        float sz = z / (1.f + __expf(-z));
        g_gbf[idx] = __float2bfloat16_rn(y * sz);
    }
}

// ---------------- launch ----------------------------------------------------
extern "C" void kernel_launch(void* const* d_in, const int* in_sizes, int n_in,
                              void* d_out, int out_size) {
    const float* x      = (const float*)d_in[0];
    const float* Wi     = (const float*)d_in[1];
    const float* bi     = (const float*)d_in[2];
    const float* conv_w = (const float*)d_in[3];
    const float* conv_b = (const float*)d_in[4];
    const float* Wdt    = (const float*)d_in[5];
    const float* bdt    = (const float*)d_in[6];
    const float* A_log  = (const float*)d_in[7];
    const float* Bm     = (const float*)d_in[8];
    const float* Cm     = (const float*)d_in[9];
    const float* Dv     = (const float*)d_in[10];
    const float* Wo     = (const float*)d_in[11];
    const float* bo     = (const float*)d_in[12];
    float* out = (float*)d_out;

    float *p_xz = nullptr, *p_dt = nullptr;
    __nv_bfloat16 *p_xbf, *p_wibf, *p_wobf, *p_wdtbf, *p_xdtbf, *p_gbf;
    cudaGetSymbolAddress((void**)&p_xz, g_xz);
    cudaGetSymbolAddress((void**)&p_dt, g_dt);
    cudaGetSymbolAddress((void**)&p_xbf,   g_xbf);
    cudaGetSymbolAddress((void**)&p_wibf,  g_wibf);
    cudaGetSymbolAddress((void**)&p_wobf,  g_wobf);
    cudaGetSymbolAddress((void**)&p_wdtbf, g_wdtbf);
    cudaGetSymbolAddress((void**)&p_xdtbf, g_xdtbf);
    cudaGetSymbolAddress((void**)&p_gbf,   g_gbf);

    cudaFuncSetAttribute(gemm_bf16<0>, cudaFuncAttributeMaxDynamicSharedMemorySize, 65536);
    cudaFuncSetAttribute(gemm_bf16<1>, cudaFuncAttributeMaxDynamicSharedMemorySize, 65536);
    cudaFuncSetAttribute(gemm_bf16<2>, cudaFuncAttributeMaxDynamicSharedMemorySize, 65536);

    // 0) prep + bf16 conversions
    prep_kernel<<<(D_INNER * D_STATE + 255) / 256, 256>>>(A_log, Dv);
    f2bf_kernel<<<(M_TOTAL * D_MODEL / 4 + 255) / 256, 256>>>(x, p_xbf, M_TOTAL * D_MODEL / 4);
    f2bf_kernel<<<(2 * D_INNER * D_MODEL / 4 + 255) / 256, 256>>>(Wi, p_wibf, 2 * D_INNER * D_MODEL / 4);
    f2bf_kernel<<<(D_MODEL * D_INNER / 4 + 255) / 256, 256>>>(Wo, p_wobf, D_MODEL * D_INNER / 4);
    f2bf_kernel<<<(D_INNER * DT_RANK / 4 + 255) / 256, 256>>>(Wdt, p_wdtbf, D_INNER * DT_RANK / 4);

    // 1) xz = x @ Wi^T + bi   (M=8192, N=4096, K=1024)
    gemm_bf16<0><<<dim3((2 * D_INNER) / 128, M_TOTAL / 128), 256, 65536>>>(
        p_xbf, D_MODEL, p_wibf, D_MODEL, bi, p_xz,
        M_TOTAL, 2 * D_INNER, D_MODEL, nullptr);

    // 2) depthwise conv + silu -> u
    conv_silu_kernel<<<dim3(D_INNER / 256, SEQ / 8, BATCH), 256>>>(conv_w, conv_b);

    // 3) dt = softplus(x_in[:, :32] @ Wdt^T + bdt)  (K=32, zero-padded to 64)
    xdt_convert_kernel<<<(M_TOTAL * DT_RANK + 255) / 256, 256>>>();
    gemm_bf16<2><<<dim3(D_INNER / 128, M_TOTAL / 128), 256, 65536>>>(
        p_xdtbf, DT_RANK, p_wdtbf, DT_RANK, bdt, p_dt,
        M_TOTAL, D_INNER, DT_RANK, nullptr);

    // 4) chunked scan
    scan1_kernel<<<dim3(D_INNER / 256, BATCH, NCHUNK), 256>>>(Bm);
    combine_kernel<<<dim3(D_INNER / 256, BATCH), 256>>>();
    scan2_kernel<<<dim3(D_INNER / 256, BATCH, NCHUNK), 256>>>(Bm, Cm);

    // 5) out = g @ Wo^T + bo + x * mean(Dv)   (M=8192, N=1024, K=2048)
    gemm_bf16<1><<<dim3(D_MODEL / 128, M_TOTAL / 128), 256, 65536>>>(
        p_gbf, D_INNER, p_wobf, D_INNER, bo, out,
        M_TOTAL, D_MODEL, D_INNER, x);
}

// round 7
// speedup vs baseline: 3.4503x; 1.1770x over previous
#include <cuda_runtime.h>
#include <cuda_bf16.h>
#include <cstdint>
#include <math.h>

#define D_MODEL 1024
#define D_STATE 16
#define D_CONV  4
#define DT_RANK 32
#define D_INNER 2048
#define BATCH   4
#define SEQ     2048
#define M_TOTAL (BATCH * SEQ)          // 8192
#define NCHUNK  32
#define CHUNK_LEN (SEQ / NCHUNK)       // 64
#define LOG2E 1.4426950408889634f

typedef unsigned int u32;

// ---------------- scratch (device globals; no allocation allowed) ----------
__device__ float g_xz[(size_t)M_TOTAL * 2 * D_INNER];   // [x_in | z] fp32
__device__ float g_u [(size_t)M_TOTAL * D_INNER];       // conv+silu out
__device__ float g_dt[(size_t)M_TOTAL * D_INNER];       // softplus(dt)
__device__ float g_A [D_INNER * D_STATE];               // -exp(A_log)*log2e
__device__ float g_hfin[(size_t)BATCH * D_INNER * NCHUNK * D_STATE];
__device__ float g_cum [(size_t)BATCH * D_INNER * NCHUNK * D_STATE];
__device__ float g_hin [(size_t)BATCH * D_INNER * NCHUNK * D_STATE];
__device__ float g_dvmean;

__device__ __nv_bfloat16 g_xbf  [(size_t)M_TOTAL * D_MODEL];
__device__ __nv_bfloat16 g_wibf [(size_t)2 * D_INNER * D_MODEL];
__device__ __nv_bfloat16 g_wobf [(size_t)D_MODEL * D_INNER];
__device__ __nv_bfloat16 g_wdtbf[(size_t)D_INNER * DT_RANK];
__device__ __nv_bfloat16 g_xdtbf[(size_t)M_TOTAL * DT_RANK];
__device__ __nv_bfloat16 g_gbf  [(size_t)M_TOTAL * D_INNER];  // y*silu(z) bf16

__device__ __forceinline__ float ex2(float x) {
    float r;
    asm("ex2.approx.f32 %0, %1;" : "=f"(r) : "f"(x));
    return r;
}

// ---------------- prep: A = -exp(A_log)*log2e, dvmean = mean(Dv) -----------
__global__ void prep_kernel(const float* __restrict__ A_log,
                            const float* __restrict__ Dv) {
    int i = blockIdx.x * blockDim.x + threadIdx.x;
    if (i < D_INNER * D_STATE) g_A[i] = -__expf(A_log[i]) * LOG2E;
    if (blockIdx.x == 0) {
        __shared__ float sdata[256];
        float s = 0.f;
        for (int j = threadIdx.x; j < D_INNER; j += 256) s += Dv[j];
        sdata[threadIdx.x] = s;
        __syncthreads();
        for (int o = 128; o > 0; o >>= 1) {
            if (threadIdx.x < o) sdata[threadIdx.x] += sdata[threadIdx.x + o];
            __syncthreads();
        }
        if (threadIdx.x == 0) g_dvmean = sdata[0] / (float)D_INNER;
    }
}

// ---------------- fp32 -> bf16 convert (vectorized) ------------------------
__global__ void f2bf_kernel(const float* __restrict__ in,
                            __nv_bfloat16* __restrict__ out, int n4) {
    int i = blockIdx.x * blockDim.x + threadIdx.x;
    if (i < n4) {
        float4 v = ((const float4*)in)[i];
        __nv_bfloat162* o = (__nv_bfloat162*)out + i * 2;
        o[0] = __nv_bfloat162(__float2bfloat16_rn(v.x), __float2bfloat16_rn(v.y));
        o[1] = __nv_bfloat162(__float2bfloat16_rn(v.z), __float2bfloat16_rn(v.w));
    }
}

// ---------------- bf16 tensor-core GEMM ------------------------------------
// C[M,N] = A[M,K] @ B[N,K]^T (+bias, epilogue MODE)
// 128x128 tile, BK=64, 3-stage cp.async, 8 warps (2Mx4N), warp tile 64x32,
// ldmatrix.x4 fragment loads, mma.sync.m16n8k16.bf16,
// 128B-row smem with XOR-16B-chunk swizzle.
// MODE 0: +bias (+side-store bf16 of n<32 cols to g_xdtbf).
// MODE 1: +bias+resid*dvmean.  MODE 2: softplus(+bias).
template <int MODE>
__global__ __launch_bounds__(256)
void gemm_bf16(const __nv_bfloat16* __restrict__ Ag, int lda,
               const __nv_bfloat16* __restrict__ Bg, int ldb,
               const float* __restrict__ bias, float* __restrict__ C,
               int M, int N, int K,
               const float* __restrict__ resid) {
    extern __shared__ __align__(16) unsigned char smem[];
    // layout: A stages [0,48K), B stages [48K,96K), 16KB per stage each
    const int tid  = threadIdx.x;
    const int lane = tid & 31;
    const int warp = tid >> 5;
    const int wm   = (warp & 1) * 64;
    const int wn   = (warp >> 1) * 32;
    const int grp  = lane >> 2;
    const int tig  = lane & 3;

    const int m0 = blockIdx.y * 128;
    const int n0 = blockIdx.x * 128;

    const u32 sbase = (u32)__cvta_generic_to_shared(smem);

    // ldmatrix per-lane addressing: lane -> (matrix mi, row-in-matrix)
    const int lrow = lane & 7;
    const int mi   = lane >> 3;      // 0..3
    const int miL  = mi & 1;
    const int miH  = mi >> 1;

    // A fragment i: matrices (rowblk=miL, khalf=miH); row = wm+16i+8*miL+lrow
    u32 aoff[4]; int asw[4];
#pragma unroll
    for (int i = 0; i < 4; i++) {
        int r = wm + 16 * i + miL * 8 + lrow;
        aoff[i] = (u32)(r * 128);
        asw[i]  = r & 7;
    }
    // B pair p (j=2p+miH): khalf=miL; row = wn+8*(2p+miH)+lrow
    u32 boff[2]; int bsw[2];
#pragma unroll
    for (int p = 0; p < 2; p++) {
        int r = wn + 8 * (2 * p + miH) + lrow;
        boff[p] = (u32)(r * 128);
        bsw[p]  = r & 7;
    }

    float acc[4][4][4];
#pragma unroll
    for (int i = 0; i < 4; i++)
#pragma unroll
        for (int j = 0; j < 4; j++)
#pragma unroll
            for (int c = 0; c < 4; c++) acc[i][j][c] = 0.f;

    const int KT = (K + 63) / 64;

#define PREFETCH(k0, st)                                                      \
    {                                                                         \
        _Pragma("unroll")                                                     \
        for (int p = 0; p < 4; p++) {                                         \
            int lin = tid + p * 256;                                          \
            int rr = lin >> 3, cc = lin & 7;                                  \
            int kg = (k0) + cc * 8;                                           \
            u32 off = (u32)(rr * 128 + ((cc ^ (rr & 7)) << 4));               \
            const __nv_bfloat16* asrc = Ag + (size_t)(m0 + rr) * lda + kg;    \
            const __nv_bfloat16* bsrc = Bg + (size_t)(n0 + rr) * ldb + kg;    \
            int sz = (kg < K) ? 16 : 0;                                       \
            if (!sz) { asrc = Ag; bsrc = Bg; }                                \
            u32 adst = sbase + (u32)((st) * 16384) + off;                     \
            u32 bdst = sbase + 49152u + (u32)((st) * 16384) + off;            \
            asm volatile("cp.async.cg.shared.global [%0], [%1], 16, %2;"      \
                         :: "r"(adst), "l"(asrc), "r"(sz));                   \
            asm volatile("cp.async.cg.shared.global [%0], [%1], 16, %2;"      \
                         :: "r"(bdst), "l"(bsrc), "r"(sz));                   \
        }                                                                     \
    }

    PREFETCH(0, 0);
    asm volatile("cp.async.commit_group;");
    if (KT > 1) PREFETCH(64, 1);
    asm volatile("cp.async.commit_group;");

    for (int kt = 0; kt < KT; kt++) {
        asm volatile("cp.async.wait_group 1;");
        __syncthreads();
        if (kt + 2 < KT) PREFETCH((kt + 2) * 64, (kt + 2) % 3);
        asm volatile("cp.async.commit_group;");

        const int st = kt % 3;
        const u32 abase = sbase + (u32)(st * 16384);
        const u32 bbase = sbase + 49152u + (u32)(st * 16384);

#pragma unroll
        for (int ks = 0; ks < 4; ks++) {
            const int chA = 2 * ks + miH;
            const int chB = 2 * ks + miL;
            // B fragments: 2 x ldmatrix.x4 -> b[j][0..1], j=0..3
            u32 bfr[4][2];
#pragma unroll
            for (int p = 0; p < 2; p++) {
                u32 addr = bbase + boff[p] + (u32)(((chB ^ bsw[p]) << 4));
                asm volatile(
                    "ldmatrix.sync.aligned.m8n8.x4.shared.b16 {%0,%1,%2,%3}, [%4];"
                    : "=r"(bfr[2 * p][0]), "=r"(bfr[2 * p][1]),
                      "=r"(bfr[2 * p + 1][0]), "=r"(bfr[2 * p + 1][1])
                    : "r"(addr));
            }
#pragma unroll
            for (int i = 0; i < 4; i++) {
                u32 addr = abase + aoff[i] + (u32)(((chA ^ asw[i]) << 4));
                u32 af0, af1, af2, af3;
                asm volatile(
                    "ldmatrix.sync.aligned.m8n8.x4.shared.b16 {%0,%1,%2,%3}, [%4];"
                    : "=r"(af0), "=r"(af1), "=r"(af2), "=r"(af3)
                    : "r"(addr));
#pragma unroll
                for (int j = 0; j < 4; j++) {
                    asm volatile(
                        "mma.sync.aligned.m16n8k16.row.col.f32.bf16.bf16.f32 "
                        "{%0,%1,%2,%3}, {%4,%5,%6,%7}, {%8,%9}, {%0,%1,%2,%3};"
                        : "+f"(acc[i][j][0]), "+f"(acc[i][j][1]),
                          "+f"(acc[i][j][2]), "+f"(acc[i][j][3])
                        : "r"(af0), "r"(af1), "r"(af2), "r"(af3),
                          "r"(bfr[j][0]), "r"(bfr[j][1]));
                }
            }
        }
        __syncthreads();
    }
#undef PREFETCH

    // epilogue
    const float dvm = (MODE == 1) ? g_dvmean : 0.f;
    const bool do_xdt = (MODE == 0) && (n0 == 0) && (wn == 0);
#pragma unroll
    for (int i = 0; i < 4; i++) {
        int m = m0 + wm + 16 * i + grp;
#pragma unroll
        for (int j = 0; j < 4; j++) {
            int n = n0 + wn + 8 * j + 2 * tig;
            float bn0 = bias[n], bn1 = bias[n + 1];
            float v0 = acc[i][j][0] + bn0;
            float v1 = acc[i][j][1] + bn1;
            float v2 = acc[i][j][2] + bn0;
            float v3 = acc[i][j][3] + bn1;
            if (MODE == 1) {
                v0 += resid[(size_t)m * N + n] * dvm;
                v1 += resid[(size_t)m * N + n + 1] * dvm;
                v2 += resid[(size_t)(m + 8) * N + n] * dvm;
                v3 += resid[(size_t)(m + 8) * N + n + 1] * dvm;
            }
            if (MODE == 2) {
                v0 = (v0 > 20.f) ? v0 : log1pf(__expf(v0));
                v1 = (v1 > 20.f) ? v1 : log1pf(__expf(v1));
                v2 = (v2 > 20.f) ? v2 : log1pf(__expf(v2));
                v3 = (v3 > 20.f) ? v3 : log1pf(__expf(v3));
            }
            *(float2*)(C + (size_t)m * N + n)       = make_float2(v0, v1);
            *(float2*)(C + (size_t)(m + 8) * N + n) = make_float2(v2, v3);
            if (do_xdt) {  // n < 32 here: side-store bf16 slice for dt GEMM
                g_xdtbf[(size_t)m * DT_RANK + n]           = __float2bfloat16_rn(v0);
                g_xdtbf[(size_t)m * DT_RANK + n + 1]       = __float2bfloat16_rn(v1);
                g_xdtbf[(size_t)(m + 8) * DT_RANK + n]     = __float2bfloat16_rn(v2);
                g_xdtbf[(size_t)(m + 8) * DT_RANK + n + 1] = __float2bfloat16_rn(v3);
            }
        }
    }
}

// ---------------- depthwise causal conv (K=4) + bias + SiLU -> u -----------
__global__ __launch_bounds__(256)
void conv_silu_kernel(const float* __restrict__ conv_w,
                      const float* __restrict__ conv_b) {
    int d  = blockIdx.x * 256 + threadIdx.x;
    int t0 = blockIdx.y * 8;
    int b  = blockIdx.z;
    const size_t row = (size_t)2 * D_INNER;
    const float* xp = g_xz + (size_t)(b * SEQ) * row + d;

    float w0 = conv_w[d * 4 + 0], w1 = conv_w[d * 4 + 1];
    float w2 = conv_w[d * 4 + 2], w3 = conv_w[d * 4 + 3];
    float bb = conv_b[d];

    float x3 = (t0 >= 3) ? xp[(size_t)(t0 - 3) * row] : 0.f;
    float x2 = (t0 >= 2) ? xp[(size_t)(t0 - 2) * row] : 0.f;
    float x1 = (t0 >= 1) ? xp[(size_t)(t0 - 1) * row] : 0.f;
#pragma unroll
    for (int tt = 0; tt < 8; tt++) {
        float x0 = xp[(size_t)(t0 + tt) * row];
        float a = bb + x3 * w0 + x2 * w1 + x1 * w2 + x0 * w3;
        float s = a / (1.f + __expf(-a));
        g_u[(size_t)(b * SEQ + t0 + tt) * D_INNER + d] = s;
        x3 = x2; x2 = x1; x1 = x0;
    }
}

// ---------------- scan pass 1: per-chunk local scan (h_in = 0) -------------
// cum-of-chunk computed as exp2(A2 * sum(dt)) instead of running product
__global__ __launch_bounds__(256)
void scan1_kernel(const float* __restrict__ Bm) {
    int d = blockIdx.x * blockDim.x + threadIdx.x;
    int b = blockIdx.y;
    int c = blockIdx.z;
    float Av[D_STATE], Bv[D_STATE], h[D_STATE];
#pragma unroll
    for (int n = 0; n < D_STATE; n++) {
        Av[n] = g_A[d * D_STATE + n];      // pre-scaled by log2e
        Bv[n] = Bm[d * D_STATE + n];
        h[n] = 0.f;
    }
    float sdt = 0.f;
    int t0 = c * CHUNK_LEN;
    for (int t = t0; t < t0 + CHUNK_LEN; t++) {
        size_t idx = (size_t)(b * SEQ + t) * D_INNER + d;
        float dtv = g_dt[idx];
        float dbu = dtv * g_u[idx];
        sdt += dtv;
#pragma unroll
        for (int n = 0; n < D_STATE; n++) {
            float dA = ex2(dtv * Av[n]);
            h[n] = h[n] * dA + dbu * Bv[n];
        }
    }
    size_t o = (((size_t)(b * D_INNER + d)) * NCHUNK + c) * D_STATE;
#pragma unroll
    for (int n = 0; n < D_STATE; n++) {
        g_hfin[o + n] = h[n];
        g_cum[o + n]  = ex2(sdt * Av[n]);
    }
}

// ---------------- sequential combine over chunks (cheap) -------------------
__global__ __launch_bounds__(256)
void combine_kernel() {
    int d = blockIdx.x * blockDim.x + threadIdx.x;
    int b = blockIdx.y;
    float H[D_STATE];
#pragma unroll
    for (int n = 0; n < D_STATE; n++) H[n] = 0.f;
    size_t base = ((size_t)(b * D_INNER + d)) * NCHUNK * D_STATE;
    for (int c = 0; c < NCHUNK; c++) {
        size_t o = base + (size_t)c * D_STATE;
#pragma unroll
        for (int n = 0; n < D_STATE; n++) g_hin[o + n] = H[n];
#pragma unroll
        for (int n = 0; n < D_STATE; n++) H[n] = g_hfin[o + n] + g_cum[o + n] * H[n];
    }
}

// ---------------- scan pass 2: full scan; g = y*silu(z) -> bf16 ------------
__global__ __launch_bounds__(256)
void scan2_kernel(const float* __restrict__ Bm, const float* __restrict__ Cm) {
    int d = blockIdx.x * blockDim.x + threadIdx.x;
    int b = blockIdx.y;
    int c = blockIdx.z;
    float Av[D_STATE], Bv[D_STATE], Cv[D_STATE], h[D_STATE];
    size_t o = (((size_t)(b * D_INNER + d)) * NCHUNK + c) * D_STATE;
#pragma unroll
    for (int n = 0; n < D_STATE; n++) {
        Av[n] = g_A[d * D_STATE + n];      // pre-scaled by log2e
        Bv[n] = Bm[d * D_STATE + n];
        Cv[n] = Cm[d * D_STATE + n];
        h[n] = g_hin[o + n];
    }
    int t0 = c * CHUNK_LEN;
    for (int t = t0; t < t0 + CHUNK_LEN; t++) {
        size_t idx = (size_t)(b * SEQ + t) * D_INNER + d;
        float dtv = g_dt[idx];
        float dbu = dtv * g_u[idx];
        float y = 0.f;
#pragma unroll
        for (int n = 0; n < D_STATE; n++) {
            float dA = ex2(dtv * Av[n]);
            h[n] = h[n] * dA + dbu * Bv[n];
            y += h[n] * Cv[n];
        }
        float z = g_xz[(size_t)(b * SEQ + t) * (2 * D_INNER) + D_INNER + d];
        float sz = z / (1.f + __expf(-z));
        g_gbf[idx] = __float2bfloat16_rn(y * sz);
    }
}

// ---------------- launch ----------------------------------------------------
extern "C" void kernel_launch(void* const* d_in, const int* in_sizes, int n_in,
                              void* d_out, int out_size) {
    const float* x      = (const float*)d_in[0];
    const float* Wi     = (const float*)d_in[1];
    const float* bi     = (const float*)d_in[2];
    const float* conv_w = (const float*)d_in[3];
    const float* conv_b = (const float*)d_in[4];
    const float* Wdt    = (const float*)d_in[5];
    const float* bdt    = (const float*)d_in[6];
    const float* A_log  = (const float*)d_in[7];
    const float* Bm     = (const float*)d_in[8];
    const float* Cm     = (const float*)d_in[9];
    const float* Dv     = (const float*)d_in[10];
    const float* Wo     = (const float*)d_in[11];
    const float* bo     = (const float*)d_in[12];
    float* out = (float*)d_out;

    float *p_xz = nullptr, *p_dt = nullptr;
    __nv_bfloat16 *p_xbf, *p_wibf, *p_wobf, *p_wdtbf, *p_xdtbf, *p_gbf;
    cudaGetSymbolAddress((void**)&p_xz, g_xz);
    cudaGetSymbolAddress((void**)&p_dt, g_dt);
    cudaGetSymbolAddress((void**)&p_xbf,   g_xbf);
    cudaGetSymbolAddress((void**)&p_wibf,  g_wibf);
    cudaGetSymbolAddress((void**)&p_wobf,  g_wobf);
    cudaGetSymbolAddress((void**)&p_wdtbf, g_wdtbf);
    cudaGetSymbolAddress((void**)&p_xdtbf, g_xdtbf);
    cudaGetSymbolAddress((void**)&p_gbf,   g_gbf);

    cudaFuncSetAttribute(gemm_bf16<0>, cudaFuncAttributeMaxDynamicSharedMemorySize, 98304);
    cudaFuncSetAttribute(gemm_bf16<1>, cudaFuncAttributeMaxDynamicSharedMemorySize, 98304);
    cudaFuncSetAttribute(gemm_bf16<2>, cudaFuncAttributeMaxDynamicSharedMemorySize, 98304);

    // 0) prep + bf16 conversions
    prep_kernel<<<(D_INNER * D_STATE + 255) / 256, 256>>>(A_log, Dv);
    f2bf_kernel<<<(M_TOTAL * D_MODEL / 4 + 255) / 256, 256>>>(x, p_xbf, M_TOTAL * D_MODEL / 4);
    f2bf_kernel<<<(2 * D_INNER * D_MODEL / 4 + 255) / 256, 256>>>(Wi, p_wibf, 2 * D_INNER * D_MODEL / 4);
    f2bf_kernel<<<(D_MODEL * D_INNER / 4 + 255) / 256, 256>>>(Wo, p_wobf, D_MODEL * D_INNER / 4);
    f2bf_kernel<<<(D_INNER * DT_RANK / 4 + 255) / 256, 256>>>(Wdt, p_wdtbf, D_INNER * DT_RANK / 4);

    // 1) xz = x @ Wi^T + bi   (M=8192, N=4096, K=1024); fuses xdt bf16 slice
    gemm_bf16<0><<<dim3((2 * D_INNER) / 128, M_TOTAL / 128), 256, 98304>>>(
        p_xbf, D_MODEL, p_wibf, D_MODEL, bi, p_xz,
        M_TOTAL, 2 * D_INNER, D_MODEL, nullptr);

    // 2) depthwise conv + silu -> u
    conv_silu_kernel<<<dim3(D_INNER / 256, SEQ / 8, BATCH), 256>>>(conv_w, conv_b);

    // 3) dt = softplus(x_in[:, :32] @ Wdt^T + bdt)  (K=32, zero-padded to 64)
    gemm_bf16<2><<<dim3(D_INNER / 128, M_TOTAL / 128), 256, 98304>>>(
        p_xdtbf, DT_RANK, p_wdtbf, DT_RANK, bdt, p_dt,
        M_TOTAL, D_INNER, DT_RANK, nullptr);

    // 4) chunked scan
    scan1_kernel<<<dim3(D_INNER / 256, BATCH, NCHUNK), 256>>>(Bm);
    combine_kernel<<<dim3(D_INNER / 256, BATCH), 256>>>();
    scan2_kernel<<<dim3(D_INNER / 256, BATCH, NCHUNK), 256>>>(Bm, Cm);

    // 5) out = g @ Wo^T + bo + x * mean(Dv)   (M=8192, N=1024, K=2048)
    gemm_bf16<1><<<dim3(D_MODEL / 128, M_TOTAL / 128), 256, 98304>>>(
        p_gbf, D_INNER, p_wobf, D_INNER, bo, out,
        M_TOTAL, D_MODEL, D_INNER, x);
}